// round 4
// baseline (speedup 1.0000x reference)
#include <cuda_runtime.h>

// FoRefLoss: sum over B rows of (dx^2 + dy^2 + wrapped_angle^2), B=8388608.
// Coalesced + deep-MLP variant: total threads = 196608 (= 2^16 * 3), so the
// grid stride is divisible by 3 and each thread's angle-component mask is
// loop-invariant. Unroll 4 with all 8 LDG.128 front-batched (MLP=8).
// Angle term in turn-space: t = 2*min(frac(|d|), 1-frac(|d|)), contribution t^2.
// Single kernel; last-arriving block reduces partials in fixed order.

#define NBLOCKS 768
#define NTHREADS 256
#define STRIDE (NBLOCKS * NTHREADS)   // 196608, divisible by 3

__device__ float g_partials[NBLOCKS];
__device__ unsigned int g_arrived = 0;

__device__ __forceinline__ float vcomp(float p, float l, bool is_angle) {
    float d = p - l;               // difference in "turns" (full circle = 1.0)
    float ad = fabsf(d);
    float f = ad - floorf(ad);     // frac in [0,1)
    float w = fminf(f, 1.0f - f);  // folded to [0, 0.5]
    return is_angle ? (w + w) : d; // angle: 2w = clamped_angle/pi; else diff
}

__device__ __forceinline__ float slot(float4 p, float4 l,
                                      bool aA, bool aB, bool aC, float acc) {
    float v;
    v = vcomp(p.x, l.x, aA); acc = fmaf(v, v, acc);
    v = vcomp(p.y, l.y, aB); acc = fmaf(v, v, acc);
    v = vcomp(p.z, l.z, aC); acc = fmaf(v, v, acc);
    v = vcomp(p.w, l.w, aA); acc = fmaf(v, v, acc);
    return acc;
}

__global__ void __launch_bounds__(NTHREADS)
foref_loss_kernel(const float4* __restrict__ pred,
                  const float4* __restrict__ lab,
                  int n4,                 // total float4 count per tensor
                  float* __restrict__ out)
{
    int tid0 = blockIdx.x * NTHREADS + threadIdx.x;

    // STRIDE % 3 == 0 -> m is invariant for this thread across all iterations.
    int m = tid0 % 3;
    const bool aA = (m == 2);   // components 0 and 3 of the float4
    const bool aB = (m == 1);   // component 1
    const bool aC = (m == 0);   // component 2

    float s0 = 0.0f, s1 = 0.0f, s2 = 0.0f, s3 = 0.0f;

    int bodies = n4 / (4 * STRIDE);   // 8 for n4 = 6291456
    int k = tid0;
    for (int it = 0; it < bodies; ++it) {
        // front-batch all 8 loads (independent -> MLP = 8)
        float4 p0 = pred[k];
        float4 p1 = pred[k +     STRIDE];
        float4 p2 = pred[k + 2 * STRIDE];
        float4 p3 = pred[k + 3 * STRIDE];
        float4 l0 = lab [k];
        float4 l1 = lab [k +     STRIDE];
        float4 l2 = lab [k + 2 * STRIDE];
        float4 l3 = lab [k + 3 * STRIDE];

        s0 = slot(p0, l0, aA, aB, aC, s0);
        s1 = slot(p1, l1, aA, aB, aC, s1);
        s2 = slot(p2, l2, aA, aB, aC, s2);
        s3 = slot(p3, l3, aA, aB, aC, s3);

        k += 4 * STRIDE;
    }
    // generic tail (empty for n4 = 6291456)
    for (; k < n4; k += STRIDE) {
        float4 p = pred[k];
        float4 l = lab[k];
        s0 = slot(p, l, aA, aB, aC, s0);
    }

    float sum = (s0 + s1) + (s2 + s3);

    // intra-block reduce
    #pragma unroll
    for (int off = 16; off > 0; off >>= 1)
        sum += __shfl_down_sync(0xFFFFFFFFu, sum, off);

    __shared__ float smem[NTHREADS / 32];
    __shared__ bool is_last;
    int lane = threadIdx.x & 31;
    int wid  = threadIdx.x >> 5;
    if (lane == 0) smem[wid] = sum;
    __syncthreads();

    if (wid == 0) {
        float v = (lane < NTHREADS / 32) ? smem[lane] : 0.0f;
        #pragma unroll
        for (int off = 4; off > 0; off >>= 1)
            v += __shfl_down_sync(0xFFFFFFFFu, v, off);
        if (lane == 0) {
            g_partials[blockIdx.x] = v;
            __threadfence();
            unsigned int t = atomicAdd(&g_arrived, 1u);
            is_last = (t == (unsigned int)(gridDim.x - 1));
        }
    }
    __syncthreads();

    if (is_last) {
        float v = 0.0f;
        for (int i = threadIdx.x; i < NBLOCKS; i += NTHREADS)
            v += g_partials[i];

        #pragma unroll
        for (int off = 16; off > 0; off >>= 1)
            v += __shfl_down_sync(0xFFFFFFFFu, v, off);

        if (lane == 0) smem[wid] = v;
        __syncthreads();

        if (wid == 0) {
            float t2 = (lane < NTHREADS / 32) ? smem[lane] : 0.0f;
            #pragma unroll
            for (int off = 4; off > 0; off >>= 1)
                t2 += __shfl_down_sync(0xFFFFFFFFu, t2, off);
            if (lane == 0) {
                out[0] = t2;
                g_arrived = 0;  // reset for next graph replay
            }
        }
    }
}

extern "C" void kernel_launch(void* const* d_in, const int* in_sizes, int n_in,
                              void* d_out, int out_size)
{
    const float4* pred = (const float4*)d_in[0];
    const float4* lab  = (const float4*)d_in[1];
    float* out = (float*)d_out;

    int n_floats = in_sizes[0];   // 25165824
    int n4 = n_floats / 4;        // 6291456

    foref_loss_kernel<<<NBLOCKS, NTHREADS>>>(pred, lab, n4, out);
}